// round 11
// baseline (speedup 1.0000x reference)
#include <cuda_runtime.h>
#include <cuda_fp16.h>

#define HH 360
#define WW 720
#define W2 360
#define HW (HH * WW)
#define BB 8
#define TYS 30
#define NITER (TYS + 14)      // 44
#define SEGS 13               // 13*28 = 364 >= 360 float2 cols
#define BANDS (HH / TYS)      // 12
#define NSTEPS 20
#define FULLM 0xffffffffu

// Scratch (allocation-free: __device__ globals).
__device__ float g_bufA[BB * HW];
__device__ float g_bufB[BB * HW];
__device__ unsigned int g_uvm[BB * HW];   // half2(u*m, v*m) per scalar point
__device__ __half g_ms[HW];               // half(m * 0.0625), 2D (batch-shared)

__device__ __forceinline__ float2 f2z() { return make_float2(0.f, 0.f); }
__device__ __forceinline__ int rclamp(int r) { return min(max(r, 0), HH - 1); }

// ---- prologue: pack u*m, v*m (fp16) and m*0.0625 (fp16), once per run
__global__ void pack_kernel(const float* __restrict__ u,
                            const float* __restrict__ v,
                            const float* __restrict__ m)
{
    const int stride = gridDim.x * blockDim.x;
    for (int j = blockIdx.x * blockDim.x + threadIdx.x; j < HW; j += stride) {
        const float mm = m[j];
        g_ms[j] = __float2half_rn(mm * 0.0625f);
#pragma unroll
        for (int b = 0; b < BB; ++b) {
            const int i = b * HW + j;
            const __half2 p = __floats2half2_rn(u[i] * mm, v[i] * mm);
            g_uvm[i] = *(const unsigned int*)&p;
        }
    }
}

// advection + horizontal (1,2,1) at 'row' from field rows Fm/Fc/Fp (row-1,row,row+1)
template <bool IN>
__device__ __forceinline__ float2 adv_h(
    const float2 Fm, const float2 Fc, const float2 Fp,
    const uint2 uvm, const float iD, const int row,
    const float sdyD, const float s2dyD, const bool zL, const bool zR)
{
    float dty0, dty1;
    if (IN) {
        dty0 = (Fp.x - Fm.x) * s2dyD;
        dty1 = (Fp.y - Fm.y) * s2dyD;
    } else {
        const float cA = (row == 0) ? sdyD  : ((row == HH - 1) ? 0.f   : s2dyD);
        const float cB = (row == 0) ? -sdyD : ((row == HH - 1) ? sdyD  : 0.f);
        const float cC = (row == 0) ? 0.f   : ((row == HH - 1) ? -sdyD : -s2dyD);
        dty0 = cA * Fp.x + cB * Fc.x + cC * Fm.x;
        dty1 = cA * Fp.y + cB * Fc.y + cC * Fm.y;
    }
    const float lf = __shfl_up_sync(FULLM, Fc.y, 1);
    const float rt = __shfl_down_sync(FULLM, Fc.x, 1);
    const float2 uv0 = __half22float2(*(const __half2*)&uvm.x);  // (u*m, v*m) col 0
    const float2 uv1 = __half22float2(*(const __half2*)&uvm.y);  // (u*m, v*m) col 1
    const float A0 = Fc.x - (uv0.x * ((Fc.y - lf) * iD) + uv0.y * dty0);
    const float A1 = Fc.y - (uv1.x * ((rt - Fc.x) * iD) + uv1.y * dty1);
    float Am = __shfl_up_sync(FULLM, A1, 1);
    float Ap = __shfl_down_sync(FULLM, A0, 1);
    Am = zL ? 0.f : Am;
    Ap = zR ? 0.f : Ap;
    float2 h;
    h.x = Am + 2.f * A0 + A1;
    h.y = A0 + 2.f * A1 + Ap;
    if (!IN && !(row >= 0 && row < HH)) { h.x = 0.f; h.y = 0.f; }
    return h;
}

// vertical (1,2,1) * (m/16) at a center row; valid=false -> 0 (y zero-padding)
__device__ __forceinline__ float2 vfilt(
    const float2 ha, const float2 hb, const float2 hc,
    const __half2 ms, const bool valid)
{
    const float2 m = __half22float2(ms);
    float2 F;
    F.x = (ha.x + 2.f * hb.x + hc.x) * m.x;
    F.y = (ha.y + 2.f * hb.y + hc.y) * m.y;
    if (!valid) { F.x = 0.f; F.y = 0.f; }
    return F;
}

// FOUR fused timesteps: 8-stage rolling pipeline down y.
template <bool IN>
__device__ __forceinline__ void run_band4(
    const float2* __restrict__ Tb, const uint2* __restrict__ Ab,
    const __half2* __restrict__ Mb, float2* __restrict__ Ob,
    const float tab0, const float tab1,
    const int y0, const int c, const bool emitl, const bool zL, const bool zR,
    const float sdyD, const float s2dyD)
{
    float2 T0, T1, TPf1, TPf2;
    uint2  aPf1, aPf2;
    __half2 mPf1, mPf2;
    {
        const int r8 = IN ? (y0 - 8) : rclamp(y0 - 8);
        const int r7 = IN ? (y0 - 7) : rclamp(y0 - 7);
        const int r6 = IN ? (y0 - 6) : rclamp(y0 - 6);
        const int r5 = IN ? (y0 - 5) : rclamp(y0 - 5);
        T0   = Tb[r8 * W2 + c];
        T1   = Tb[r7 * W2 + c];
        TPf1 = Tb[r6 * W2 + c];
        TPf2 = Tb[r5 * W2 + c];
        aPf1 = Ab[r7 * W2 + c];
        aPf2 = Ab[r6 * W2 + c];
        mPf1 = Mb[r7 * W2 + c];
        mPf2 = Mb[r6 * W2 + c];
    }

    // operand rings (constant indices after full unroll -> registers)
    uint2   aR[7];
    __half2 mR[8];
#pragma unroll
    for (int i = 0; i < 7; ++i) aR[i] = make_uint2(0u, 0u);
#pragma unroll
    for (int i = 0; i < 8; ++i) mR[i] = __floats2half2_rn(0.f, 0.f);

    float2 h1a = f2z(), h1b = f2z(), h1c = f2z();
    float2 F1a = f2z(), F1b = f2z(), F1c = f2z();
    float2 h2a = f2z(), h2b = f2z(), h2c = f2z();
    float2 F2a = f2z(), F2b = f2z(), F2c = f2z();
    float2 h3a = f2z(), h3b = f2z(), h3c = f2z();
    float2 F3a = f2z(), F3b = f2z(), F3c = f2z();
    float2 h4a = f2z(), h4b = f2z(), h4c = f2z();

#pragma unroll
    for (int k = 0; k < NITER; ++k) {
        const int a = y0 - 7 + k;       // step-1 advection row

        // ring shifts (register renames under full unroll)
#pragma unroll
        for (int i = 6; i > 0; --i) aR[i] = aR[i - 1];
        aR[0] = aPf1;  aPf1 = aPf2;
#pragma unroll
        for (int i = 7; i > 0; --i) mR[i] = mR[i - 1];
        mR[0] = mPf1;  mPf1 = mPf2;
        const float2 T2 = TPf1;  TPf1 = TPf2;

        // 2-deep prefetch (T: a+3, uvm/ms: a+2)
        {
            const int rT = IN ? (a + 3) : rclamp(a + 3);
            const int rU = IN ? (a + 2) : rclamp(a + 2);
            TPf2 = Tb[rT * W2 + c];
            aPf2 = Ab[rU * W2 + c];
            mPf2 = Mb[rU * W2 + c];
        }

        // per-row DT/(2dx) from lane tables (compile-time lane indices)
        const float iD0 = (k     < 32) ? __shfl_sync(FULLM, tab0, k)
                                       : __shfl_sync(FULLM, tab1, k - 32);

        // ---- stage 1: step-1 advection+h at row a
        h1a = h1b; h1b = h1c;
        h1c = adv_h<IN>(T0, T1, T2, aR[0], iD0, a, sdyD, s2dyD, zL, zR);

        // ---- stage 2: step-1 vfilter -> F1 at row a-1
        F1a = F1b; F1b = F1c;
        if (k >= 2)
            F1c = vfilt(h1a, h1b, h1c, mR[1],
                        IN ? true : ((unsigned)(a - 1) < (unsigned)HH));

        // ---- stage 3: step-2 advection+h at row a-2
        h2a = h2b; h2b = h2c;
        if (k >= 4) {
            const float iD2 = (k - 2 < 32) ? __shfl_sync(FULLM, tab0, k - 2)
                                           : __shfl_sync(FULLM, tab1, k - 34);
            h2c = adv_h<IN>(F1a, F1b, F1c, aR[2], iD2, a - 2, sdyD, s2dyD, zL, zR);
        }

        // ---- stage 4: step-2 vfilter -> F2 at row a-3
        F2a = F2b; F2b = F2c;
        if (k >= 6)
            F2c = vfilt(h2a, h2b, h2c, mR[3],
                        IN ? true : ((unsigned)(a - 3) < (unsigned)HH));

        // ---- stage 5: step-3 advection+h at row a-4
        h3a = h3b; h3b = h3c;
        if (k >= 8) {
            const float iD4 = (k - 4 < 32) ? __shfl_sync(FULLM, tab0, k - 4)
                                           : __shfl_sync(FULLM, tab1, k - 36);
            h3c = adv_h<IN>(F2a, F2b, F2c, aR[4], iD4, a - 4, sdyD, s2dyD, zL, zR);
        }

        // ---- stage 6: step-3 vfilter -> F3 at row a-5
        F3a = F3b; F3b = F3c;
        if (k >= 10)
            F3c = vfilt(h3a, h3b, h3c, mR[5],
                        IN ? true : ((unsigned)(a - 5) < (unsigned)HH));

        // ---- stage 7: step-4 advection+h at row a-6
        h4a = h4b; h4b = h4c;
        if (k >= 12) {
            const float iD6 = (k - 6 < 32) ? __shfl_sync(FULLM, tab0, k - 6)
                                           : __shfl_sync(FULLM, tab1, k - 38);
            h4c = adv_h<IN>(F3a, F3b, F3c, aR[6], iD6, a - 6, sdyD, s2dyD, zL, zR);
        }

        // ---- stage 8: step-4 vfilter -> emit row e = a-7 (always in [0,HH))
        if (k >= 14) {
            if (emitl) {
                const int e = a - 7;        // in [y0, y0+TYS)
                const float2 m = __half22float2(mR[7]);
                float2 o;
                o.x = (h4a.x + 2.f * h4b.x + h4c.x) * m.x;
                o.y = (h4a.y + 2.f * h4b.y + h4c.y) * m.y;
                Ob[e * W2 + c] = o;
            }
        }

        T0 = T1; T1 = T2;
    }
}

// One warp per block.
__global__ __launch_bounds__(32) void ocean_step4(
    const float* __restrict__ Tin, float* __restrict__ Tout,
    const float* __restrict__ lat, const float* __restrict__ lon)
{
    const int lane = threadIdx.x;
    const int ws   = blockIdx.x;
    const int seg  = ws % SEGS;
    const int rem  = ws / SEGS;
    const int band = rem % BANDS;
    const int b    = rem / BANDS;
    const int y0   = band * TYS;

    // lane -> float2 column (wrapped). Lanes 2..29 emit.
    int c = seg * 28 - 2 + lane;
    c += (c < 0) ? W2 : 0;
    c -= (c >= W2) ? W2 : 0;
    const bool emitl = (lane >= 2) && (lane <= 29);
    const bool zL = (c == 0);
    const bool zR = (c == W2 - 1);

    const float DEG2RAD = 0.017453292519943295f;
    const float RE = 6371000.0f, DTC = 600.0f;
    const float dlat = lat[1] - lat[0];
    const float dlon = lon[1] - lon[0];
    const float dy   = RE * DEG2RAD * fabsf(dlat);
    const float sgn  = (dlat > 0.f) ? 1.f : -1.f;
    const float sdyD  = DTC * sgn / dy;
    const float s2dyD = DTC * sgn / (2.f * dy);
    const float xden = 2.f * RE * DEG2RAD * dlon;

    // two lane-register DT/(2dx) tables: idx i -> row y0-7+i  (i = 0..43)
    const int tr0 = rclamp(y0 - 7 + lane);
    const int tr1 = rclamp(y0 + 25 + lane);
    const float tab0 = __fdividef(DTC, xden * __cosf(lat[tr0] * DEG2RAD));
    const float tab1 = __fdividef(DTC, xden * __cosf(lat[tr1] * DEG2RAD));

    const float2*  Tb = (const float2*)(Tin + (size_t)b * HW);
    const uint2*   Ab = (const uint2*)(g_uvm + (size_t)b * HW);
    const __half2* Mb = (const __half2*)g_ms;
    float2*        Ob = (float2*)(Tout + (size_t)b * HW);

    // interior: advection rows a in [y0-7, y0+TYS+6] all in [1, HH-2]
    if (y0 >= 8 && (y0 + TYS + 6) <= HH - 2)
        run_band4<true >(Tb, Ab, Mb, Ob, tab0, tab1, y0, c, emitl, zL, zR, sdyD, s2dyD);
    else
        run_band4<false>(Tb, Ab, Mb, Ob, tab0, tab1, y0, c, emitl, zL, zR, sdyD, s2dyD);
}

extern "C" void kernel_launch(void* const* d_in, const int* in_sizes, int n_in,
                              void* d_out, int out_size)
{
    const float* T    = (const float*)d_in[0];
    const float* ug   = (const float*)d_in[1];
    const float* vg   = (const float*)d_in[2];
    const float* lat  = (const float*)d_in[3];
    const float* lon  = (const float*)d_in[4];
    const float* mask = (const float*)d_in[5];
    float* out = (float*)d_out;

    float *bufA = nullptr, *bufB = nullptr;
    cudaGetSymbolAddress((void**)&bufA, g_bufA);
    cudaGetSymbolAddress((void**)&bufB, g_bufB);

    pack_kernel<<<296, 256>>>(ug, vg, mask);

    const int nblocks = SEGS * BANDS * BB;   // 13*12*8 = 1248 one-warp blocks
    dim3 grid(nblocks);
    dim3 block(32);

    const float* cur = T;
    const int nquads = NSTEPS / 4;           // 5 fused launches
    for (int p = 0; p < nquads; ++p) {
        float* dst = (p == nquads - 1) ? out : ((p & 1) ? bufB : bufA);
        ocean_step4<<<grid, block>>>(cur, dst, lat, lon);
        cur = dst;
    }
}

// round 12
// speedup vs baseline: 1.2688x; 1.2688x over previous
#include <cuda_runtime.h>
#include <cuda_fp16.h>

#define HH 360
#define WW 720
#define W4 180            // float4 columns per row
#define HW (HH * WW)
#define BB 8
#define TYS 15
#define NITER (TYS + 6)   // 21
#define NTAB  (NITER + 2) // 23 rows: y0-5 .. y0+TYS+2
#define SEGS 7            // 7*28 = 196 >= 180 float4 cols (wrap, dup writes identical)
#define BANDS (HH / TYS)  // 24
#define NSTEPS 20
#define FULLM 0xffffffffu

// Scratch (allocation-free: __device__ globals). Declared as vector types for
// guaranteed 16B/8B alignment of the float4/uint4/uint2 accesses.
__device__ float4 g_bufA[BB * HW / 4];
__device__ float4 g_bufB[BB * HW / 4];
__device__ uint4  g_uvm4[BB * HW / 4];   // half2(u*m, v*m) per scalar point
__device__ uint2  g_ms4[HW / 4];         // half(m*0.0625) per scalar point (2D)

__device__ __forceinline__ float4 f4z() { return make_float4(0.f, 0.f, 0.f, 0.f); }
__device__ __forceinline__ int rclamp(int r) { return min(max(r, 0), HH - 1); }

// ---- prologue: pack u*m, v*m (fp16) and m*0.0625 (fp16), once per replay
__global__ void pack_kernel(const float* __restrict__ u,
                            const float* __restrict__ v,
                            const float* __restrict__ m)
{
    unsigned int* uvm = (unsigned int*)g_uvm4;
    __half*       ms  = (__half*)g_ms4;
    const int stride = gridDim.x * blockDim.x;
    for (int j = blockIdx.x * blockDim.x + threadIdx.x; j < HW; j += stride) {
        const float mm = m[j];
        ms[j] = __float2half_rn(mm * 0.0625f);
#pragma unroll
        for (int b = 0; b < BB; ++b) {
            const int i = b * HW + j;
            const __half2 p = __floats2half2_rn(u[i] * mm, v[i] * mm);
            uvm[i] = *(const unsigned int*)&p;
        }
    }
}

// advection + horizontal (1,2,1) for 4 scalar cols at 'row'
template <bool IN>
__device__ __forceinline__ float4 adv_h4(
    const float4 Fm, const float4 Fc, const float4 Fp,
    const uint4 uvm, const float iD, const int row,
    const float sdyD, const float s2dyD, const bool zL, const bool zR)
{
    float4 dty;
    if (IN) {
        dty.x = (Fp.x - Fm.x) * s2dyD;
        dty.y = (Fp.y - Fm.y) * s2dyD;
        dty.z = (Fp.z - Fm.z) * s2dyD;
        dty.w = (Fp.w - Fm.w) * s2dyD;
    } else {
        const float cA = (row == 0) ? sdyD  : ((row == HH - 1) ? 0.f   : s2dyD);
        const float cB = (row == 0) ? -sdyD : ((row == HH - 1) ? sdyD  : 0.f);
        const float cC = (row == 0) ? 0.f   : ((row == HH - 1) ? -sdyD : -s2dyD);
        dty.x = cA * Fp.x + cB * Fc.x + cC * Fm.x;
        dty.y = cA * Fp.y + cB * Fc.y + cC * Fm.y;
        dty.z = cA * Fp.z + cB * Fc.z + cC * Fm.z;
        dty.w = cA * Fp.w + cB * Fc.w + cC * Fm.w;
    }
    const float lf = __shfl_up_sync(FULLM, Fc.w, 1);    // scalar col 4q-1
    const float rt = __shfl_down_sync(FULLM, Fc.x, 1);  // scalar col 4q+4 (periodic)
    const float dtx0 = (Fc.y - lf)   * iD;
    const float dtx1 = (Fc.z - Fc.x) * iD;
    const float dtx2 = (Fc.w - Fc.y) * iD;
    const float dtx3 = (rt   - Fc.z) * iD;
    const float2 uv0 = __half22float2(*(const __half2*)&uvm.x);
    const float2 uv1 = __half22float2(*(const __half2*)&uvm.y);
    const float2 uv2 = __half22float2(*(const __half2*)&uvm.z);
    const float2 uv3 = __half22float2(*(const __half2*)&uvm.w);
    const float A0 = Fc.x - (uv0.x * dtx0 + uv0.y * dty.x);
    const float A1 = Fc.y - (uv1.x * dtx1 + uv1.y * dty.y);
    const float A2 = Fc.z - (uv2.x * dtx2 + uv2.y * dty.z);
    const float A3 = Fc.w - (uv3.x * dtx3 + uv3.y * dty.w);
    float Am = __shfl_up_sync(FULLM, A3, 1);
    float Ap = __shfl_down_sync(FULLM, A0, 1);
    Am = zL ? 0.f : Am;                 // conv zero-pads x (not periodic)
    Ap = zR ? 0.f : Ap;
    float4 h;
    h.x = Am + 2.f * A0 + A1;
    h.y = A0 + 2.f * A1 + A2;
    h.z = A1 + 2.f * A2 + A3;
    h.w = A2 + 2.f * A3 + Ap;
    if (!IN && !(row >= 0 && row < HH)) h = f4z();
    return h;
}

// vertical (1,2,1) * (m/16) for 4 scalar cols; valid=false -> 0 (y zero-pad)
__device__ __forceinline__ float4 vfilt4(
    const float4 ha, const float4 hb, const float4 hc,
    const uint2 ms, const bool valid)
{
    const float2 m01 = __half22float2(*(const __half2*)&ms.x);
    const float2 m23 = __half22float2(*(const __half2*)&ms.y);
    float4 F;
    F.x = (ha.x + 2.f * hb.x + hc.x) * m01.x;
    F.y = (ha.y + 2.f * hb.y + hc.y) * m01.y;
    F.z = (ha.z + 2.f * hb.z + hc.z) * m23.x;
    F.w = (ha.w + 2.f * hb.w + hc.w) * m23.y;
    if (!valid) F = f4z();
    return F;
}

// Two fused timesteps, 6-stage rolling pipeline down y, float4 lanes.
template <bool IN>
__device__ __forceinline__ void run_band(
    const float4* __restrict__ Tb, const uint4* __restrict__ Ab,
    const uint2* __restrict__ Mb, float4* __restrict__ Ob,
    const float tabI,
    const int y0, const int q, const bool emitl, const bool zL, const bool zR,
    const float sdyD, const float s2dyD)
{
    float4 T0, T1, TPf1, TPf2;
    uint4  aPf1, aPf2;
    uint2  mPf1, mPf2;
    {
        const int r0 = IN ? (y0 - 4) : rclamp(y0 - 4);
        const int r1 = IN ? (y0 - 3) : rclamp(y0 - 3);
        const int r2 = IN ? (y0 - 2) : rclamp(y0 - 2);
        const int r3 = IN ? (y0 - 1) : rclamp(y0 - 1);
        T0   = Tb[r0 * W4 + q];
        T1   = Tb[r1 * W4 + q];
        TPf1 = Tb[r2 * W4 + q];
        TPf2 = Tb[r3 * W4 + q];
        aPf1 = Ab[r1 * W4 + q];
        aPf2 = Ab[r2 * W4 + q];
        mPf1 = Mb[r1 * W4 + q];
        mPf2 = Mb[r2 * W4 + q];
    }

    float4 h1a = f4z(), h1b = f4z(), h1c = f4z();
    float4 F1a = f4z(), F1b = f4z(), F1c = f4z();
    float4 h2a = f4z(), h2b = f4z(), h2c = f4z();
    uint4  aR0 = make_uint4(0,0,0,0), aR1 = aR0, aR2 = aR0;  // uvm rows a, a-1, a-2
    uint2  mR0 = make_uint2(0,0), mR1 = mR0, mR2 = mR0, mR3 = mR0; // ms rows a..a-3

#pragma unroll
    for (int k = 0; k < NITER; ++k) {
        const int a = y0 - 3 + k;       // step-1 advection row

        // ring shifts (renamed by full unroll)
        mR3 = mR2; mR2 = mR1; mR1 = mR0; mR0 = mPf1; mPf1 = mPf2;
        aR2 = aR1; aR1 = aR0; aR0 = aPf1; aPf1 = aPf2;
        const float4 T2 = TPf1;  TPf1 = TPf2;

        // 2-deep prefetch (T: a+3, uvm/ms: a+2)
        {
            const int rT = IN ? (a + 3) : rclamp(a + 3);
            const int rU = IN ? (a + 2) : rclamp(a + 2);
            TPf2 = Tb[rT * W4 + q];
            aPf2 = Ab[rU * W4 + q];
            mPf2 = Mb[rU * W4 + q];
        }

        // ---- stage 1: step-1 advection + h at row a
        h1a = h1b; h1b = h1c;
        {
            const float iA = __shfl_sync(FULLM, tabI, k + 2);
            h1c = adv_h4<IN>(T0, T1, T2, aR0, iA, a, sdyD, s2dyD, zL, zR);
        }

        // ---- stage 2: step-1 vfilter -> F1 at row f = a-1
        F1a = F1b; F1b = F1c;
        if (k >= 2)
            F1c = vfilt4(h1a, h1b, h1c, mR1,
                         IN ? true : ((unsigned)(a - 1) < (unsigned)HH));

        // ---- stage 3: step-2 advection + h at row g = a-2
        h2a = h2b; h2b = h2c;
        if (k >= 4) {
            const float iG = __shfl_sync(FULLM, tabI, k);
            h2c = adv_h4<IN>(F1a, F1b, F1c, aR2, iG, a - 2, sdyD, s2dyD, zL, zR);
        }

        // ---- stage 4: step-2 vfilter -> emit row e = a-3
        if (k >= 6) {
            if (emitl) {
                const int e = a - 3;        // in [y0, y0+TYS)
                Ob[e * W4 + q] = vfilt4(h2a, h2b, h2c, mR3, true);
            }
        }

        T0 = T1; T1 = T2;
    }
}

// One warp per block.
__global__ __launch_bounds__(32) void ocean_step2(
    const float4* __restrict__ Tin, float4* __restrict__ Tout,
    const float* __restrict__ lat, const float* __restrict__ lon)
{
    const int lane = threadIdx.x;
    const int ws   = blockIdx.x;
    const int seg  = ws % SEGS;
    const int rem  = ws / SEGS;
    const int band = rem % BANDS;
    const int b    = rem / BANDS;
    const int y0   = band * TYS;

    // lane -> float4 column (wrapped). Lanes 2..29 emit.
    int q = seg * 28 - 2 + lane;
    q += (q < 0) ? W4 : 0;
    q -= (q >= W4) ? W4 : 0;
    const bool emitl = (lane >= 2) && (lane <= 29);
    const bool zL = (q == 0);          // conv zero-pad left of scalar col 0
    const bool zR = (q == W4 - 1);     // conv zero-pad right of scalar col 719

    const float DEG2RAD = 0.017453292519943295f;
    const float RE = 6371000.0f, DTC = 600.0f;
    const float dlat = lat[1] - lat[0];
    const float dlon = lon[1] - lon[0];
    const float dy   = RE * DEG2RAD * fabsf(dlat);
    const float sgn  = (dlat > 0.f) ? 1.f : -1.f;
    const float sdyD  = DTC * sgn / dy;           // DT folded in
    const float s2dyD = DTC * sgn / (2.f * dy);
    const float xden = 2.f * RE * DEG2RAD * dlon;

    // per-lane DT/(2dx) table: lane i holds row y0-5+i (clamped); read via shfl
    const int tr = rclamp(y0 - 5 + min(lane, NTAB - 1));
    const float tabI = __fdividef(DTC, xden * __cosf(lat[tr] * DEG2RAD));

    const float4* Tb = Tin + (size_t)b * (HW / 4);
    const uint4*  Ab = g_uvm4 + (size_t)b * (HW / 4);
    const uint2*  Mb = g_ms4;
    float4*       Ob = Tout + (size_t)b * (HW / 4);

    if (band > 0 && band < BANDS - 1)
        run_band<true >(Tb, Ab, Mb, Ob, tabI, y0, q, emitl, zL, zR, sdyD, s2dyD);
    else
        run_band<false>(Tb, Ab, Mb, Ob, tabI, y0, q, emitl, zL, zR, sdyD, s2dyD);
}

extern "C" void kernel_launch(void* const* d_in, const int* in_sizes, int n_in,
                              void* d_out, int out_size)
{
    const float* T    = (const float*)d_in[0];
    const float* ug   = (const float*)d_in[1];
    const float* vg   = (const float*)d_in[2];
    const float* lat  = (const float*)d_in[3];
    const float* lon  = (const float*)d_in[4];
    const float* mask = (const float*)d_in[5];
    float* out = (float*)d_out;

    float4 *bufA = nullptr, *bufB = nullptr;
    cudaGetSymbolAddress((void**)&bufA, g_bufA);
    cudaGetSymbolAddress((void**)&bufB, g_bufB);

    pack_kernel<<<296, 256>>>(ug, vg, mask);

    const int nblocks = SEGS * BANDS * BB;   // 7*24*8 = 1344 one-warp blocks
    dim3 grid(nblocks);
    dim3 block(32);

    const float4* cur = (const float4*)T;
    const int npairs = NSTEPS / 2;           // 10 fused launches
    for (int p = 0; p < npairs; ++p) {
        float4* dst = (p == npairs - 1) ? (float4*)out : ((p & 1) ? bufB : bufA);
        ocean_step2<<<grid, block>>>(cur, dst, lat, lon);
        cur = dst;
    }
}

// round 13
// speedup vs baseline: 1.2934x; 1.0194x over previous
#include <cuda_runtime.h>
#include <cuda_fp16.h>

#define HH 360
#define WW 720
#define W2 360
#define HW (HH * WW)
#define BB 8
#define TYS 15
#define BANDS (HH / TYS)  // 24
#define NSTEPS 20
#define FULLM 0xffffffffu

// step3 geometry: 3 halo lanes/side, 26 emit float2-cols/warp
#define NIT3 (TYS + 10)   // 25
#define SEG3 14           // 14*26 = 364 >= 360 (wrap, dup writes identical)
// step2 geometry: 2 halo lanes/side, 28 emit float2-cols/warp
#define NIT2 (TYS + 6)    // 21
#define SEG2 13

// Scratch (allocation-free: __device__ globals).
__device__ float g_bufA[BB * HW];
__device__ float g_bufB[BB * HW];
__device__ unsigned int g_uvm[BB * HW];   // half2(u*m, v*m) per scalar point
__device__ __half g_ms[HW];               // half(m * 0.0625), 2D (batch-shared)

__device__ __forceinline__ float2 f2z() { return make_float2(0.f, 0.f); }
__device__ __forceinline__ int rclamp(int r) { return min(max(r, 0), HH - 1); }

// ---- prologue: pack u*m, v*m (fp16) and m*0.0625 (fp16)
__global__ void pack_kernel(const float* __restrict__ u,
                            const float* __restrict__ v,
                            const float* __restrict__ m)
{
    const int stride = gridDim.x * blockDim.x;
    for (int j = blockIdx.x * blockDim.x + threadIdx.x; j < HW; j += stride) {
        const float mm = m[j];
        g_ms[j] = __float2half_rn(mm * 0.0625f);
#pragma unroll
        for (int b = 0; b < BB; ++b) {
            const int i = b * HW + j;
            const __half2 p = __floats2half2_rn(u[i] * mm, v[i] * mm);
            g_uvm[i] = *(const unsigned int*)&p;
        }
    }
}

// advection + horizontal (1,2,1) for 2 scalar cols at 'row'
template <bool IN>
__device__ __forceinline__ float2 adv_h(
    const float2 Fm, const float2 Fc, const float2 Fp,
    const uint2 uvm, const float iD, const int row,
    const float sdyD, const float s2dyD, const bool zL, const bool zR)
{
    float dty0, dty1;
    if (IN) {
        dty0 = (Fp.x - Fm.x) * s2dyD;
        dty1 = (Fp.y - Fm.y) * s2dyD;
    } else {
        const float cA = (row == 0) ? sdyD  : ((row == HH - 1) ? 0.f   : s2dyD);
        const float cB = (row == 0) ? -sdyD : ((row == HH - 1) ? sdyD  : 0.f);
        const float cC = (row == 0) ? 0.f   : ((row == HH - 1) ? -sdyD : -s2dyD);
        dty0 = cA * Fp.x + cB * Fc.x + cC * Fm.x;
        dty1 = cA * Fp.y + cB * Fc.y + cC * Fm.y;
    }
    const float lf = __shfl_up_sync(FULLM, Fc.y, 1);
    const float rt = __shfl_down_sync(FULLM, Fc.x, 1);
    const float2 uv0 = __half22float2(*(const __half2*)&uvm.x);
    const float2 uv1 = __half22float2(*(const __half2*)&uvm.y);
    const float A0 = Fc.x - (uv0.x * ((Fc.y - lf) * iD) + uv0.y * dty0);
    const float A1 = Fc.y - (uv1.x * ((rt - Fc.x) * iD) + uv1.y * dty1);
    float Am = __shfl_up_sync(FULLM, A1, 1);
    float Ap = __shfl_down_sync(FULLM, A0, 1);
    Am = zL ? 0.f : Am;
    Ap = zR ? 0.f : Ap;
    float2 h;
    h.x = Am + 2.f * A0 + A1;
    h.y = A0 + 2.f * A1 + Ap;
    if (!IN && !(row >= 0 && row < HH)) { h.x = 0.f; h.y = 0.f; }
    return h;
}

__device__ __forceinline__ float2 vfilt(
    const float2 ha, const float2 hb, const float2 hc,
    const __half2 ms, const bool valid)
{
    const float2 m = __half22float2(ms);
    float2 F;
    F.x = (ha.x + 2.f * hb.x + hc.x) * m.x;
    F.y = (ha.y + 2.f * hb.y + hc.y) * m.y;
    if (!valid) { F.x = 0.f; F.y = 0.f; }
    return F;
}

// ======================= THREE fused timesteps =======================
template <bool IN>
__device__ __forceinline__ void run_band3(
    const float2* __restrict__ Tb, const uint2* __restrict__ Ab,
    const __half2* __restrict__ Mb, float2* __restrict__ Ob,
    const float tabI,
    const int y0, const int c, const bool emitl, const bool zL, const bool zR,
    const float sdyD, const float s2dyD)
{
    float2 T0, T1, TPf1, TPf2;
    uint2  aPf1, aPf2;
    __half2 mPf1, mPf2;
    {
        const int r0 = IN ? (y0 - 6) : rclamp(y0 - 6);
        const int r1 = IN ? (y0 - 5) : rclamp(y0 - 5);
        const int r2 = IN ? (y0 - 4) : rclamp(y0 - 4);
        const int r3 = IN ? (y0 - 3) : rclamp(y0 - 3);
        T0   = Tb[r0 * W2 + c];
        T1   = Tb[r1 * W2 + c];
        TPf1 = Tb[r2 * W2 + c];
        TPf2 = Tb[r3 * W2 + c];
        aPf1 = Ab[r1 * W2 + c];
        aPf2 = Ab[r2 * W2 + c];
        mPf1 = Mb[r1 * W2 + c];
        mPf2 = Mb[r2 * W2 + c];
    }

    float2 h1a = f2z(), h1b = f2z(), h1c = f2z();
    float2 F1a = f2z(), F1b = f2z(), F1c = f2z();
    float2 h2a = f2z(), h2b = f2z(), h2c = f2z();
    float2 F2a = f2z(), F2b = f2z(), F2c = f2z();
    float2 h3a = f2z(), h3b = f2z(), h3c = f2z();
    // uvm ring: aR[i] = row a-i, need i = 0, 2, 4
    uint2  aR0 = make_uint2(0,0), aR1 = aR0, aR2 = aR0, aR3 = aR0, aR4 = aR0;
    // ms ring: mR[i] = row a-i, need i = 1, 3, 5
    __half2 z16 = __floats2half2_rn(0.f, 0.f);
    __half2 mR0 = z16, mR1 = z16, mR2 = z16, mR3 = z16, mR4 = z16, mR5 = z16;

#pragma unroll
    for (int k = 0; k < NIT3; ++k) {
        const int a = y0 - 5 + k;       // step-1 advection row

        // ring shifts (register renames under full unroll)
        mR5 = mR4; mR4 = mR3; mR3 = mR2; mR2 = mR1; mR1 = mR0;
        mR0 = mPf1; mPf1 = mPf2;
        aR4 = aR3; aR3 = aR2; aR2 = aR1; aR1 = aR0;
        aR0 = aPf1; aPf1 = aPf2;
        const float2 T2 = TPf1;  TPf1 = TPf2;

        // 2-deep prefetch (T: a+3, uvm/ms: a+2)
        {
            const int rT = IN ? (a + 3) : rclamp(a + 3);
            const int rU = IN ? (a + 2) : rclamp(a + 2);
            TPf2 = Tb[rT * W2 + c];
            aPf2 = Ab[rU * W2 + c];
            mPf2 = Mb[rU * W2 + c];
        }

        // ---- stage 1: step-1 advection + h at row a          (table idx k+4)
        h1a = h1b; h1b = h1c;
        {
            const float iA = __shfl_sync(FULLM, tabI, k + 4);
            h1c = adv_h<IN>(T0, T1, T2, aR0, iA, a, sdyD, s2dyD, zL, zR);
        }

        // ---- stage 2: step-1 vfilter -> F1 at row a-1
        F1a = F1b; F1b = F1c;
        if (k >= 2)
            F1c = vfilt(h1a, h1b, h1c, mR1,
                        IN ? true : ((unsigned)(a - 1) < (unsigned)HH));

        // ---- stage 3: step-2 advection + h at row a-2        (table idx k+2)
        h2a = h2b; h2b = h2c;
        if (k >= 4) {
            const float iG = __shfl_sync(FULLM, tabI, k + 2);
            h2c = adv_h<IN>(F1a, F1b, F1c, aR2, iG, a - 2, sdyD, s2dyD, zL, zR);
        }

        // ---- stage 4: step-2 vfilter -> F2 at row a-3
        F2a = F2b; F2b = F2c;
        if (k >= 6)
            F2c = vfilt(h2a, h2b, h2c, mR3,
                        IN ? true : ((unsigned)(a - 3) < (unsigned)HH));

        // ---- stage 5: step-3 advection + h at row a-4        (table idx k)
        h3a = h3b; h3b = h3c;
        if (k >= 8) {
            const float iJ = __shfl_sync(FULLM, tabI, k);
            h3c = adv_h<IN>(F2a, F2b, F2c, aR4, iJ, a - 4, sdyD, s2dyD, zL, zR);
        }

        // ---- stage 6: step-3 vfilter -> emit row e = a-5
        if (k >= 10) {
            if (emitl) {
                const int e = a - 5;        // in [y0, y0+TYS)
                Ob[e * W2 + c] = vfilt(h3a, h3b, h3c, mR5, true);
            }
        }

        T0 = T1; T1 = T2;
    }
}

__global__ __launch_bounds__(32) void ocean_step3(
    const float* __restrict__ Tin, float* __restrict__ Tout,
    const float* __restrict__ lat, const float* __restrict__ lon)
{
    const int lane = threadIdx.x;
    const int ws   = blockIdx.x;
    const int seg  = ws % SEG3;
    const int rem  = ws / SEG3;
    const int band = rem % BANDS;
    const int b    = rem / BANDS;
    const int y0   = band * TYS;

    // lane -> float2 column (wrapped). Lanes 3..28 emit (3 halo lanes/side).
    int c = seg * 26 - 3 + lane;
    c += (c < 0) ? W2 : 0;
    c -= (c >= W2) ? W2 : 0;
    const bool emitl = (lane >= 3) && (lane <= 28);
    const bool zL = (c == 0);
    const bool zR = (c == W2 - 1);

    const float DEG2RAD = 0.017453292519943295f;
    const float RE = 6371000.0f, DTC = 600.0f;
    const float dlat = lat[1] - lat[0];
    const float dlon = lon[1] - lon[0];
    const float dy   = RE * DEG2RAD * fabsf(dlat);
    const float sgn  = (dlat > 0.f) ? 1.f : -1.f;
    const float sdyD  = DTC * sgn / dy;
    const float s2dyD = DTC * sgn / (2.f * dy);
    const float xden = 2.f * RE * DEG2RAD * dlon;

    // per-lane DT/(2dx) table: lane i holds row y0-9+i (clamped)
    const int tr = rclamp(y0 - 9 + lane);
    const float tabI = __fdividef(DTC, xden * __cosf(lat[tr] * DEG2RAD));

    const float2*  Tb = (const float2*)(Tin + (size_t)b * HW);
    const uint2*   Ab = (const uint2*)(g_uvm + (size_t)b * HW);
    const __half2* Mb = (const __half2*)g_ms;
    float2*        Ob = (float2*)(Tout + (size_t)b * HW);

    // interior: advection rows [y0-9, y0+19] within [1, HH-2]
    if (band > 0 && band < BANDS - 1)
        run_band3<true >(Tb, Ab, Mb, Ob, tabI, y0, c, emitl, zL, zR, sdyD, s2dyD);
    else
        run_band3<false>(Tb, Ab, Mb, Ob, tabI, y0, c, emitl, zL, zR, sdyD, s2dyD);
}

// ======================= TWO fused timesteps (R10 winner) =======================
template <bool IN>
__device__ __forceinline__ void run_band2(
    const float2* __restrict__ Tb, const uint2* __restrict__ Ab,
    const __half2* __restrict__ Mb, float2* __restrict__ Ob,
    const float tabI,
    const int y0, const int c, const bool emitl, const bool zL, const bool zR,
    const float sdyD, const float s2dyD)
{
    float2 T0, T1, TPf1, TPf2;
    uint2  aPf1, aPf2;
    __half2 mPf1, mPf2;
    {
        const int r0 = IN ? (y0 - 4) : rclamp(y0 - 4);
        const int r1 = IN ? (y0 - 3) : rclamp(y0 - 3);
        const int r2 = IN ? (y0 - 2) : rclamp(y0 - 2);
        const int r3 = IN ? (y0 - 1) : rclamp(y0 - 1);
        T0   = Tb[r0 * W2 + c];
        T1   = Tb[r1 * W2 + c];
        TPf1 = Tb[r2 * W2 + c];
        TPf2 = Tb[r3 * W2 + c];
        aPf1 = Ab[r1 * W2 + c];
        aPf2 = Ab[r2 * W2 + c];
        mPf1 = Mb[r1 * W2 + c];
        mPf2 = Mb[r2 * W2 + c];
    }

    float2 h1a = f2z(), h1b = f2z(), h1c = f2z();
    float2 F1a = f2z(), F1b = f2z(), F1c = f2z();
    float2 h2a = f2z(), h2b = f2z(), h2c = f2z();
    uint2  aR0 = make_uint2(0,0), aR1 = aR0, aR2 = aR0;
    __half2 z16 = __floats2half2_rn(0.f, 0.f);
    __half2 mR0 = z16, mR1 = z16, mR2 = z16, mR3 = z16;

#pragma unroll
    for (int k = 0; k < NIT2; ++k) {
        const int a = y0 - 3 + k;

        mR3 = mR2; mR2 = mR1; mR1 = mR0; mR0 = mPf1; mPf1 = mPf2;
        aR2 = aR1; aR1 = aR0; aR0 = aPf1; aPf1 = aPf2;
        const float2 T2 = TPf1;  TPf1 = TPf2;

        {
            const int rT = IN ? (a + 3) : rclamp(a + 3);
            const int rU = IN ? (a + 2) : rclamp(a + 2);
            TPf2 = Tb[rT * W2 + c];
            aPf2 = Ab[rU * W2 + c];
            mPf2 = Mb[rU * W2 + c];
        }

        h1a = h1b; h1b = h1c;
        {
            const float iA = __shfl_sync(FULLM, tabI, k + 2);
            h1c = adv_h<IN>(T0, T1, T2, aR0, iA, a, sdyD, s2dyD, zL, zR);
        }

        F1a = F1b; F1b = F1c;
        if (k >= 2)
            F1c = vfilt(h1a, h1b, h1c, mR1,
                        IN ? true : ((unsigned)(a - 1) < (unsigned)HH));

        h2a = h2b; h2b = h2c;
        if (k >= 4) {
            const float iG = __shfl_sync(FULLM, tabI, k);
            h2c = adv_h<IN>(F1a, F1b, F1c, aR2, iG, a - 2, sdyD, s2dyD, zL, zR);
        }

        if (k >= 6) {
            if (emitl) {
                const int e = a - 3;
                Ob[e * W2 + c] = vfilt(h2a, h2b, h2c, mR3, true);
            }
        }

        T0 = T1; T1 = T2;
    }
}

__global__ __launch_bounds__(32) void ocean_step2(
    const float* __restrict__ Tin, float* __restrict__ Tout,
    const float* __restrict__ lat, const float* __restrict__ lon)
{
    const int lane = threadIdx.x;
    const int ws   = blockIdx.x;
    const int seg  = ws % SEG2;
    const int rem  = ws / SEG2;
    const int band = rem % BANDS;
    const int b    = rem / BANDS;
    const int y0   = band * TYS;

    int c = seg * 28 - 2 + lane;
    c += (c < 0) ? W2 : 0;
    c -= (c >= W2) ? W2 : 0;
    const bool emitl = (lane >= 2) && (lane <= 29);
    const bool zL = (c == 0);
    const bool zR = (c == W2 - 1);

    const float DEG2RAD = 0.017453292519943295f;
    const float RE = 6371000.0f, DTC = 600.0f;
    const float dlat = lat[1] - lat[0];
    const float dlon = lon[1] - lon[0];
    const float dy   = RE * DEG2RAD * fabsf(dlat);
    const float sgn  = (dlat > 0.f) ? 1.f : -1.f;
    const float sdyD  = DTC * sgn / dy;
    const float s2dyD = DTC * sgn / (2.f * dy);
    const float xden = 2.f * RE * DEG2RAD * dlon;

    const int tr = rclamp(y0 - 5 + min(lane, NIT2 + 1));
    const float tabI = __fdividef(DTC, xden * __cosf(lat[tr] * DEG2RAD));

    const float2*  Tb = (const float2*)(Tin + (size_t)b * HW);
    const uint2*   Ab = (const uint2*)(g_uvm + (size_t)b * HW);
    const __half2* Mb = (const __half2*)g_ms;
    float2*        Ob = (float2*)(Tout + (size_t)b * HW);

    if (band > 0 && band < BANDS - 1)
        run_band2<true >(Tb, Ab, Mb, Ob, tabI, y0, c, emitl, zL, zR, sdyD, s2dyD);
    else
        run_band2<false>(Tb, Ab, Mb, Ob, tabI, y0, c, emitl, zL, zR, sdyD, s2dyD);
}

extern "C" void kernel_launch(void* const* d_in, const int* in_sizes, int n_in,
                              void* d_out, int out_size)
{
    const float* T    = (const float*)d_in[0];
    const float* ug   = (const float*)d_in[1];
    const float* vg   = (const float*)d_in[2];
    const float* lat  = (const float*)d_in[3];
    const float* lon  = (const float*)d_in[4];
    const float* mask = (const float*)d_in[5];
    float* out = (float*)d_out;

    float *bufA = nullptr, *bufB = nullptr;
    cudaGetSymbolAddress((void**)&bufA, g_bufA);
    cudaGetSymbolAddress((void**)&bufB, g_bufB);

    pack_kernel<<<296, 256>>>(ug, vg, mask);

    dim3 grid3(SEG3 * BANDS * BB);   // 14*24*8 = 2688 one-warp blocks
    dim3 grid2(SEG2 * BANDS * BB);   // 13*24*8 = 2496
    dim3 block(32);

    // 6 x 3-step + 1 x 2-step = 20 steps, 7 launches
    const float* cur = T;
    float* dst;
    for (int p = 0; p < 6; ++p) {
        dst = (p & 1) ? bufB : bufA;
        ocean_step3<<<grid3, block>>>(cur, dst, lat, lon);
        cur = dst;
    }
    ocean_step2<<<grid2, block>>>(cur, out, lat, lon);
}